// round 7
// baseline (speedup 1.0000x reference)
#include <cuda_runtime.h>
#include <math.h>
#include <stdint.h>

#define EMBED   1024
#define HEADS   16
#define HD      64
#define NB      12
#define SEQ     257
#define BATCH   32
#define MROWS   (BATCH*SEQ)      // 8224
#define HIDDEN  2816

// ---------------- scratch (device globals; no allocations allowed) ----------
__device__ __align__(256) float g_a[MROWS*EMBED];        // normalized activations (tf32-rounded)
__device__ __align__(256) float g_qkv[MROWS*3*EMBED];    // qkv / reused as w3-output
__device__ __align__(256) float g_o[MROWS*EMBED];        // attention output (tf32-rounded)
__device__ __align__(256) float g_u[MROWS*HIDDEN];       // silu(u)*v (tf32-rounded)
__device__ __align__(256) float g_fc[SEQ*32*2];          // rope cos/sin table
__device__ __align__(256) float g_xr[8192*768];          // tf32-rounded x
__device__ __align__(256) float g_cr[32*1024];           // tf32-rounded cond

// tf32-rounded weights (same layout as inputs, no transpose), one arena
#define OFF_QKV   ((size_t)0)
#define OFF_WO    (OFF_QKV + (size_t)NB*1024*3072)
#define OFF_W1    (OFF_WO  + (size_t)NB*1024*1024)
#define OFF_W3    (OFF_W1  + (size_t)NB*1024*HIDDEN)
#define OFF_W2    (OFF_W3  + (size_t)NB*1024*HIDDEN)
#define OFF_PATCH (OFF_W2  + (size_t)NB*HIDDEN*1024)
#define OFF_COND  (OFF_PATCH + (size_t)768*1024)
#define WT_TOTAL  (OFF_COND + (size_t)1024*1024)
__device__ __align__(256) float g_wt[WT_TOTAL];

// ---------------- helpers ----------------------------------------------------
__device__ __forceinline__ uint32_t smem_u32(const void* p) {
    uint32_t a;
    asm("{ .reg .u64 t; cvta.to.shared.u64 t, %1; cvt.u32.u64 %0, t; }" : "=r"(a) : "l"(p));
    return a;
}
__device__ __forceinline__ uint32_t f2tf(float x) {
    uint32_t r; asm("cvt.rna.tf32.f32 %0, %1;" : "=r"(r) : "f"(x)); return r;
}
__device__ __forceinline__ float rndf(float x) { return __uint_as_float(f2tf(x)); }

__device__ __forceinline__ void mma_tf32(float c[4], const uint32_t a[4],
                                         const uint32_t b[2]) {
    asm volatile(
        "mma.sync.aligned.m16n8k8.row.col.f32.tf32.tf32.f32 "
        "{%0,%1,%2,%3}, {%4,%5,%6,%7}, {%8,%9}, {%0,%1,%2,%3};"
        : "+f"(c[0]), "+f"(c[1]), "+f"(c[2]), "+f"(c[3])
        : "r"(a[0]), "r"(a[1]), "r"(a[2]), "r"(a[3]), "r"(b[0]), "r"(b[1]));
}

__device__ __forceinline__ void cp16(uint32_t dst, const void* src, int sz) {
    asm volatile("cp.async.cg.shared.global [%0], [%1], 16, %2;"
        :: "r"(dst), "l"(src), "r"(sz) : "memory");
}

// ---------------- pipelined TF32 tensor-core GEMM ----------------------------
// C[M,N] = A[M,K] @ B[K,N] (+bias) (+res). A,B pre-rounded to tf32 values.
// CTA tile 256x128, BK=32, 3-stage cp.async pipeline. 8 warps (4m x 2n),
// warp tile 64x64 (balances 128B/cyc smem crossbar against HMMA issue).
// A staged [m][k] stride 36 (bank 4g+tg); B staged [k][n] stride 136 (bank 8tg+g).
#define BM     256
#define BN     128
#define A_ST   36
#define B_ST   136
#define A_FL   (BM*A_ST)             // 9216 floats
#define B_FL   (32*B_ST)             // 4352 floats
#define ST_FL  (A_FL+B_FL)           // 13568 floats = 54272 B per stage
#define G_SMEM (3*ST_FL*4)           // 162816 bytes

__global__ __launch_bounds__(256) void ar_gemm_tf32(
    const float* __restrict__ A, const float* __restrict__ B,
    const float* __restrict__ bias, const float* __restrict__ res,
    float* __restrict__ C, int M, int N, int K)
{
    extern __shared__ float sm[];
    uint32_t sm_u = smem_u32(sm);

    int tid = threadIdx.x, lane = tid & 31, warp = tid >> 5;
    int wm = warp >> 1, wn = warp & 1;              // 4x2 warp grid, 64x64 each
    int bm = blockIdx.y * BM, bn = blockIdx.x * BN;
    int g = lane >> 2, tg = lane & 3;

    float acc[4][8][4];
    #pragma unroll
    for (int i = 0; i < 4; i++)
        #pragma unroll
        for (int j = 0; j < 8; j++)
            #pragma unroll
            for (int t = 0; t < 4; t++) acc[i][j][t] = 0.f;

    const int NC = K >> 5;

    auto load_chunk = [&](int cidx) {
        int s = cidx % 3, k0 = cidx << 5;
        uint32_t st = sm_u + (uint32_t)(s * ST_FL) * 4u;
        #pragma unroll
        for (int i = 0; i < 8; i++) {              // A: 2048 x 16B
            int idx = tid + (i << 8);
            int r = idx >> 3, cc = idx & 7;
            uint32_t dst = st + (uint32_t)(r * A_ST + cc * 4) * 4u;
            int gm = bm + r;
            bool v = (gm < M);
            const float* src = A + (size_t)(v ? gm : 0) * K + k0 + cc * 4;
            cp16(dst, src, v ? 16 : 0);
        }
        #pragma unroll
        for (int i = 0; i < 4; i++) {              // B: 1024 x 16B
            int idx = tid + (i << 8);
            int r = idx >> 5, cc = idx & 31;
            uint32_t dst = st + (uint32_t)(A_FL + r * B_ST + cc * 4) * 4u;
            const float* src = B + (size_t)(k0 + r) * N + bn + cc * 4;
            cp16(dst, src, 16);
        }
    };

    auto compute = [&](int s) {
        const float* Ab = sm + s * ST_FL;
        const float* Bb = Ab + A_FL;
        int m0 = wm * 64 + g;
        int n0 = wn * 64 + g;
        #pragma unroll
        for (int kb = 0; kb < 32; kb += 8) {
            uint32_t af[4][4];
            #pragma unroll
            for (int t = 0; t < 4; t++) {
                const float* ar0 = Ab + (m0 + t * 16) * A_ST + kb + tg;
                af[t][0] = __float_as_uint(ar0[0]);
                af[t][1] = __float_as_uint(ar0[8 * A_ST]);
                af[t][2] = __float_as_uint(ar0[4]);
                af[t][3] = __float_as_uint(ar0[8 * A_ST + 4]);
            }
            uint32_t bf[8][2];
            #pragma unroll
            for (int t = 0; t < 8; t++) {
                const float* br = Bb + (kb + tg) * B_ST + n0 + t * 8;
                bf[t][0] = __float_as_uint(br[0]);
                bf[t][1] = __float_as_uint(br[4 * B_ST]);
            }
            #pragma unroll
            for (int mt = 0; mt < 4; mt++)
                #pragma unroll
                for (int nt = 0; nt < 8; nt++)
                    mma_tf32(acc[mt][nt], af[mt], bf[nt]);
        }
    };

    load_chunk(0);
    asm volatile("cp.async.commit_group;" ::: "memory");
    load_chunk(1);
    asm volatile("cp.async.commit_group;" ::: "memory");
    load_chunk(2);
    asm volatile("cp.async.commit_group;" ::: "memory");

    for (int c = 0; c < NC; c++) {
        asm volatile("cp.async.wait_group 2;" ::: "memory");
        __syncthreads();
        compute(c % 3);
        __syncthreads();
        if (c + 3 < NC) load_chunk(c + 3);
        asm volatile("cp.async.commit_group;" ::: "memory");
    }

    // epilogue
    #pragma unroll
    for (int mt = 0; mt < 4; mt++) {
        int rbase = bm + wm * 64 + mt * 16 + g;
        #pragma unroll
        for (int half = 0; half < 2; half++) {
            int r = rbase + half * 8;
            if (r >= M) continue;
            #pragma unroll
            for (int nt = 0; nt < 8; nt++) {
                int cl = bn + wn * 64 + nt * 8 + 2 * tg;
                float2 v;
                v.x = acc[mt][nt][half * 2 + 0];
                v.y = acc[mt][nt][half * 2 + 1];
                if (bias) { v.x += bias[cl]; v.y += bias[cl + 1]; }
                if (res) {
                    float2 rr = *(const float2*)(res + (size_t)r * N + cl);
                    v.x += rr.x; v.y += rr.y;
                }
                *(float2*)(C + (size_t)r * N + cl) = v;
            }
        }
    }
}

// ---------------- vectorized tf32 round-copy ---------------------------------
__global__ void ar_round4(const float* __restrict__ in, float* __restrict__ out,
                          size_t n4) {
    size_t i = (size_t)blockIdx.x * blockDim.x + threadIdx.x;
    if (i < n4) {
        float4 v = ((const float4*)in)[i];
        v.x = rndf(v.x); v.y = rndf(v.y); v.z = rndf(v.z); v.w = rndf(v.w);
        ((float4*)out)[i] = v;
    }
}

// ---------------- reductions ------------------------------------------------
__device__ __forceinline__ float block_sum(float v, float* red) {
    int tid = threadIdx.x;
    #pragma unroll
    for (int o = 16; o > 0; o >>= 1) v += __shfl_xor_sync(0xffffffffu, v, o);
    if ((tid & 31) == 0) red[tid >> 5] = v;
    __syncthreads();
    if (tid == 0) {
        float s = red[0];
        int nw = blockDim.x >> 5;
        for (int i = 1; i < nw; i++) s += red[i];
        red[0] = s;
    }
    __syncthreads();
    float r = red[0];
    __syncthreads();
    return r;
}

__device__ __forceinline__ float block_max(float v, float* red) {
    int tid = threadIdx.x;
    #pragma unroll
    for (int o = 16; o > 0; o >>= 1) v = fmaxf(v, __shfl_xor_sync(0xffffffffu, v, o));
    if ((tid & 31) == 0) red[tid >> 5] = v;
    __syncthreads();
    if (tid == 0) {
        float s = red[0];
        int nw = blockDim.x >> 5;
        for (int i = 1; i < nw; i++) s = fmaxf(s, red[i]);
        red[0] = s;
    }
    __syncthreads();
    float r = red[0];
    __syncthreads();
    return r;
}

// ---------------- rope frequency table --------------------------------------
__global__ void ar_freqs(float* __restrict__ fc) {
    int t = blockIdx.x * blockDim.x + threadIdx.x;
    if (t >= SEQ * 32) return;
    int p = t >> 5, j = t & 31;
    float c = 0.f, s = 0.f;
    if (p > 0) {                       // cls token keeps cos=sin=0 (ref!)
        int pp = p - 1, yy = pp >> 4, xx = pp & 15;
        int i = j & 15;
        float fr = powf(10000.0f, -(float)i * (1.0f / 16.0f));
        float tt = (j < 16) ? (float)yy : (float)xx;
        float ang = tt * fr;
        c = cosf(ang); s = sinf(ang);
    }
    fc[2 * t] = c;
    fc[2 * t + 1] = s;
}

// ---------------- assemble (cond | patch) + pos + LayerNorm ------------------
__global__ __launch_bounds__(256) void ar_assemble_ln(
    const float* __restrict__ patch, const float* __restrict__ condr,
    const float* __restrict__ pos, const float* __restrict__ g,
    const float* __restrict__ bta, float* __restrict__ h)
{
    __shared__ float buf[EMBED];
    __shared__ float red[8];
    int m = blockIdx.x, tid = threadIdx.x;
    int b = m / SEQ, s = m % SEQ;
    const float* src = (s == 0) ? (condr + (size_t)b * EMBED)
                                : (patch + ((size_t)(b * 256 + s - 1)) * EMBED);
    float lsum = 0.f;
    for (int d = tid; d < EMBED; d += 256) {
        float v = src[d] + pos[(size_t)s * EMBED + d];
        buf[d] = v; lsum += v;
    }
    float mean = block_sum(lsum, red) * (1.f / EMBED);
    float ls2 = 0.f;
    for (int d = tid; d < EMBED; d += 256) {
        float dv = buf[d] - mean; ls2 += dv * dv;
    }
    float var = block_sum(ls2, red) * (1.f / EMBED);
    float rinv = rsqrtf(var + 1e-6f);
    for (int d = tid; d < EMBED; d += 256)
        h[(size_t)m * EMBED + d] = (buf[d] - mean) * rinv * g[d] + bta[d];
}

// ---------------- RMSNorm (tf32-rounded output: feeds GEMM A) ----------------
__global__ __launch_bounds__(256) void ar_rmsnorm(
    const float* __restrict__ x, const float* __restrict__ w, float* __restrict__ out)
{
    __shared__ float buf[EMBED];
    __shared__ float red[8];
    int m = blockIdx.x, tid = threadIdx.x;
    const float* xr = x + (size_t)m * EMBED;
    float ss = 0.f;
    for (int d = tid; d < EMBED; d += 256) {
        float v = xr[d]; buf[d] = v; ss += v * v;
    }
    ss = block_sum(ss, red);
    float r = rsqrtf(ss * (1.f / EMBED) + 1e-5f);
    for (int d = tid; d < EMBED; d += 256)
        out[(size_t)m * EMBED + d] = rndf(buf[d] * r * w[d]);
}

// ---------------- rope (in-place on q and k halves of qkv) -------------------
__global__ void ar_rope(float* __restrict__ qkv, const float* __restrict__ fc) {
    int t = blockIdx.x * blockDim.x + threadIdx.x;
    if (t >= MROWS * 512) return;
    int m = t >> 9, r = t & 511;
    int hh = r >> 5, j = r & 31;
    int s = m % SEQ;
    float c  = fc[(s * 32 + j) * 2];
    float sn = fc[(s * 32 + j) * 2 + 1];
    float* q = qkv + (size_t)m * (3 * EMBED) + hh * HD + 2 * j;
    float x0 = q[0], x1 = q[1];
    q[0] = x0 * c - x1 * sn;
    q[1] = x1 * c + x0 * sn;
    float* k = q + EMBED;
    x0 = k[0]; x1 = k[1];
    k[0] = x0 * c - x1 * sn;
    k[1] = x1 * c + x0 * sn;
}

// ---------------- attention: rows 0..255, whole K/V in smem -----------------
__device__ __forceinline__ void ar_attn_row(
    int qrow, int b, int h, const float* __restrict__ qkv,
    const float* __restrict__ Ks, const float* __restrict__ Vs,
    float* __restrict__ o)
{
    const float4* qp = (const float4*)(qkv + ((size_t)(b * SEQ + qrow)) * (3 * EMBED) + h * HD);
    float4 qv[16];
    #pragma unroll
    for (int i = 0; i < 16; i++) qv[i] = qp[i];
    float acc[64];
    #pragma unroll
    for (int d = 0; d < 64; d++) acc[d] = 0.f;
    float mx = -1e30f, l = 0.f;
    for (int j = 0; j <= qrow; j++) {
        const float4* kr = (const float4*)(Ks + j * 64);
        float s0 = 0.f, s1 = 0.f, s2 = 0.f, s3 = 0.f;
        #pragma unroll
        for (int i = 0; i < 16; i++) {
            float4 kk = kr[i];
            s0 = fmaf(qv[i].x, kk.x, s0);
            s1 = fmaf(qv[i].y, kk.y, s1);
            s2 = fmaf(qv[i].z, kk.z, s2);
            s3 = fmaf(qv[i].w, kk.w, s3);
        }
        float s = ((s0 + s1) + (s2 + s3)) * 0.125f;
        float nm = fmaxf(mx, s);
        float corr = __expf(mx - nm);
        float p = __expf(s - nm);
        l = l * corr + p;
        const float4* vr = (const float4*)(Vs + j * 64);
        #pragma unroll
        for (int i = 0; i < 16; i++) {
            float4 vv = vr[i];
            acc[4*i+0] = fmaf(acc[4*i+0], corr, p * vv.x);
            acc[4*i+1] = fmaf(acc[4*i+1], corr, p * vv.y);
            acc[4*i+2] = fmaf(acc[4*i+2], corr, p * vv.z);
            acc[4*i+3] = fmaf(acc[4*i+3], corr, p * vv.w);
        }
        mx = nm;
    }
    float inv = 1.f / l;
    float* op = o + ((size_t)(b * SEQ + qrow)) * EMBED + h * HD;
    #pragma unroll
    for (int d = 0; d < 64; d++) op[d] = rndf(acc[d] * inv);
}

__global__ __launch_bounds__(128) void ar_attn(const float* __restrict__ qkv,
                                               float* __restrict__ o)
{
    extern __shared__ float smkv[];
    float* Ks = smkv;
    float* Vs = smkv + SEQ * 64;
    int h = blockIdx.x, b = blockIdx.y, tid = threadIdx.x;
    const float* base = qkv + (size_t)b * SEQ * (3 * EMBED) + EMBED + h * HD;
    for (int idx = tid; idx < SEQ * 16; idx += 128) {
        int s = idx >> 4, c = idx & 15;
        *(float4*)(Ks + s * 64 + c * 4) = *(const float4*)(base + (size_t)s * (3 * EMBED) + c * 4);
        *(float4*)(Vs + s * 64 + c * 4) = *(const float4*)(base + EMBED + (size_t)s * (3 * EMBED) + c * 4);
    }
    __syncthreads();
    ar_attn_row(tid, b, h, qkv, Ks, Vs, o);
    ar_attn_row(255 - tid, b, h, qkv, Ks, Vs, o);
}

// ---------------- attention row 256 (longest row, j-parallel) ---------------
__global__ __launch_bounds__(256) void ar_attn_last(const float* __restrict__ qkv,
                                                    float* __restrict__ o)
{
    __shared__ float qs[64];
    __shared__ float sc[SEQ];
    __shared__ float red[8];
    __shared__ float part[4][64];
    int h = blockIdx.x, b = blockIdx.y, tid = threadIdx.x;
    const float* qrow = qkv + ((size_t)(b * SEQ + 256)) * (3 * EMBED) + h * HD;
    if (tid < 64) qs[tid] = qrow[tid];
    __syncthreads();
    const float* kbase = qkv + (size_t)b * SEQ * (3 * EMBED) + EMBED + (size_t)h * HD;
    float lm = -1e30f;
    for (int j = tid; j < SEQ; j += 256) {
        const float* kr = kbase + (size_t)j * (3 * EMBED);
        float s = 0.f;
        #pragma unroll
        for (int d = 0; d < 64; d++) s = fmaf(qs[d], kr[d], s);
        s *= 0.125f;
        sc[j] = s;
        lm = fmaxf(lm, s);
    }
    float M = block_max(lm, red);
    float ls = 0.f;
    for (int j = tid; j < SEQ; j += 256) {
        float p = __expf(sc[j] - M);
        sc[j] = p;
        ls += p;
    }
    float L = block_sum(ls, red);
    int d = tid & 63, c = tid >> 6;
    const float* vbase = kbase + EMBED;
    float a = 0.f;
    for (int j = c; j < SEQ; j += 4)
        a = fmaf(sc[j], vbase[(size_t)j * (3 * EMBED) + d], a);
    part[c][d] = a;
    __syncthreads();
    if (tid < 64) {
        float s = part[0][tid] + part[1][tid] + part[2][tid] + part[3][tid];
        o[((size_t)(b * SEQ + 256)) * EMBED + h * HD + tid] = rndf(s / L);
    }
}

// ---------------- fused silu(u) * v (rounded: feeds GEMM A) -----------------
__global__ void ar_silu_mul(float* __restrict__ u, const float* __restrict__ v, int n) {
    int i = blockIdx.x * blockDim.x + threadIdx.x;
    if (i < n) {
        float uu = u[i];
        float s = uu / (1.f + __expf(-uu));
        u[i] = rndf(s * v[i]);
    }
}

// ---------------- host orchestration ----------------------------------------
static inline void launch_gemm(const float* A, const float* B, const float* bias,
                               const float* res, float* C, int M, int N, int K) {
    dim3 grid(N / BN, (M + BM - 1) / BM);
    ar_gemm_tf32<<<grid, 256, G_SMEM>>>(A, B, bias, res, C, M, N, K);
}

static inline void launch_round(const float* in, float* out, size_t n) {
    size_t n4 = n / 4;
    ar_round4<<<(unsigned)((n4 + 255) / 256), 256>>>(in, out, n4);
}

extern "C" void kernel_launch(void* const* d_in, const int* in_sizes, int n_in,
                              void* d_out, int out_size)
{
    const float* x       = (const float*)d_in[0];
    const float* cond    = (const float*)d_in[1];
    const float* patch_w = (const float*)d_in[2];
    const float* patch_b = (const float*)d_in[3];
    const float* ln_g    = (const float*)d_in[4];
    const float* ln_b    = (const float*)d_in[5];
    const float* pos     = (const float*)d_in[6];
    const float* cond_w  = (const float*)d_in[7];
    const float* cond_b  = (const float*)d_in[8];
    const float* wqkv    = (const float*)d_in[9];
    const float* wo      = (const float*)d_in[10];
    const float* w1      = (const float*)d_in[11];
    const float* w2      = (const float*)d_in[12];
    const float* w3      = (const float*)d_in[13];
    const float* anw     = (const float*)d_in[14];
    const float* fnw     = (const float*)d_in[15];
    float* h = (float*)d_out;

    float *pa, *pqkv, *po, *pu, *pfc, *pxr, *pcr, *pwt;
    cudaGetSymbolAddress((void**)&pa,   g_a);
    cudaGetSymbolAddress((void**)&pqkv, g_qkv);
    cudaGetSymbolAddress((void**)&po,   g_o);
    cudaGetSymbolAddress((void**)&pu,   g_u);
    cudaGetSymbolAddress((void**)&pfc,  g_fc);
    cudaGetSymbolAddress((void**)&pxr,  g_xr);
    cudaGetSymbolAddress((void**)&pcr,  g_cr);
    cudaGetSymbolAddress((void**)&pwt,  g_wt);

    cudaFuncSetAttribute(ar_attn, cudaFuncAttributeMaxDynamicSharedMemorySize,
                         SEQ * 64 * 2 * (int)sizeof(float));
    cudaFuncSetAttribute(ar_gemm_tf32, cudaFuncAttributeMaxDynamicSharedMemorySize,
                         G_SMEM);

    float* qkvR   = pwt + OFF_QKV;
    float* woR    = pwt + OFF_WO;
    float* w1R    = pwt + OFF_W1;
    float* w3R    = pwt + OFF_W3;
    float* w2R    = pwt + OFF_W2;
    float* patchR = pwt + OFF_PATCH;
    float* condR  = pwt + OFF_COND;

    // tf32 round-copy all weights + A-side raw inputs (once per launch)
    launch_round(wqkv,    qkvR,   (size_t)NB * 1024 * 3072);
    launch_round(wo,      woR,    (size_t)NB * 1024 * 1024);
    launch_round(w1,      w1R,    (size_t)NB * 1024 * HIDDEN);
    launch_round(w3,      w3R,    (size_t)NB * 1024 * HIDDEN);
    launch_round(w2,      w2R,    (size_t)NB * HIDDEN * 1024);
    launch_round(patch_w, patchR, (size_t)768 * 1024);
    launch_round(cond_w,  condR,  (size_t)1024 * 1024);
    launch_round(x,       pxr,    (size_t)8192 * 768);
    launch_round(cond,    pcr,    (size_t)32 * 1024);

    // rope table
    ar_freqs<<<(SEQ * 32 + 255) / 256, 256>>>(pfc);
    // patch embed -> g_a ; cond embed -> g_o
    launch_gemm(pxr, patchR, patch_b, nullptr, pa, BATCH * 256, EMBED, 768);
    launch_gemm(pcr, condR, cond_b, nullptr, po, BATCH, EMBED, EMBED);
    // assemble + pos + layernorm -> h (d_out)
    ar_assemble_ln<<<MROWS, 256>>>(pa, po, pos, ln_g, ln_b, h);

    for (int l = 0; l < NB; l++) {
        float* qkv_l = qkvR + (size_t)l * 1024 * 3072;
        float* wo_l  = woR  + (size_t)l * 1024 * 1024;
        float* w1_l  = w1R  + (size_t)l * 1024 * HIDDEN;
        float* w3_l  = w3R  + (size_t)l * 1024 * HIDDEN;
        float* w2_l  = w2R  + (size_t)l * HIDDEN * 1024;

        ar_rmsnorm<<<MROWS, 256>>>(h, anw + (size_t)l * EMBED, pa);
        launch_gemm(pa, qkv_l, nullptr, nullptr, pqkv, MROWS, 3 * EMBED, EMBED);
        ar_rope<<<(MROWS * 512 + 255) / 256, 256>>>(pqkv, pfc);
        ar_attn<<<dim3(HEADS, BATCH), 128, SEQ * 64 * 2 * (int)sizeof(float)>>>(pqkv, po);
        ar_attn_last<<<dim3(HEADS, BATCH), 256>>>(pqkv, po);
        launch_gemm(po, wo_l, nullptr, h, h, MROWS, EMBED, EMBED);

        ar_rmsnorm<<<MROWS, 256>>>(h, fnw + (size_t)l * EMBED, pa);
        launch_gemm(pa, w1_l, nullptr, nullptr, pu, MROWS, HIDDEN, EMBED);
        launch_gemm(pa, w3_l, nullptr, nullptr, pqkv, MROWS, HIDDEN, EMBED);
        ar_silu_mul<<<(MROWS * HIDDEN + 255) / 256, 256>>>(pu, pqkv, MROWS * HIDDEN);
        launch_gemm(pu, w2_l, nullptr, h, h, MROWS, EMBED, HIDDEN);
    }
}

// round 9
// speedup vs baseline: 1.0414x; 1.0414x over previous
#include <cuda_runtime.h>
#include <math.h>
#include <stdint.h>

#define EMBED   1024
#define HEADS   16
#define HD      64
#define NB      12
#define SEQ     257
#define BATCH   32
#define MROWS   (BATCH*SEQ)      // 8224
#define HIDDEN  2816

// ---------------- scratch (device globals; no allocations allowed) ----------
__device__ __align__(256) float g_a[MROWS*EMBED];        // normalized activations (tf32-rounded)
__device__ __align__(256) float g_qkv[MROWS*3*EMBED];    // qkv / reused as w3-output
__device__ __align__(256) float g_o[MROWS*EMBED];        // attention output (tf32-rounded)
__device__ __align__(256) float g_u[MROWS*HIDDEN];       // silu(u)*v (tf32-rounded)
__device__ __align__(256) float g_fc[SEQ*32*2];          // rope cos/sin table
__device__ __align__(256) float g_xr[8192*768];          // tf32-rounded x
__device__ __align__(256) float g_cr[32*1024];           // tf32-rounded cond

// tf32-rounded weights (same layout as inputs, no transpose), one arena
#define OFF_QKV   ((size_t)0)
#define OFF_WO    (OFF_QKV + (size_t)NB*1024*3072)
#define OFF_W1    (OFF_WO  + (size_t)NB*1024*1024)
#define OFF_W3    (OFF_W1  + (size_t)NB*1024*HIDDEN)
#define OFF_W2    (OFF_W3  + (size_t)NB*1024*HIDDEN)
#define OFF_PATCH (OFF_W2  + (size_t)NB*HIDDEN*1024)
#define OFF_COND  (OFF_PATCH + (size_t)768*1024)
#define WT_TOTAL  (OFF_COND + (size_t)1024*1024)
__device__ __align__(256) float g_wt[WT_TOTAL];

// ---------------- helpers ----------------------------------------------------
__device__ __forceinline__ uint32_t smem_u32(const void* p) {
    uint32_t a;
    asm("{ .reg .u64 t; cvta.to.shared.u64 t, %1; cvt.u32.u64 %0, t; }" : "=r"(a) : "l"(p));
    return a;
}
__device__ __forceinline__ uint32_t f2tf(float x) {
    uint32_t r; asm("cvt.rna.tf32.f32 %0, %1;" : "=r"(r) : "f"(x)); return r;
}
__device__ __forceinline__ float rndf(float x) { return __uint_as_float(f2tf(x)); }

__device__ __forceinline__ void mma_tf32(float c[4], const uint32_t a[4],
                                         const uint32_t b[2]) {
    asm volatile(
        "mma.sync.aligned.m16n8k8.row.col.f32.tf32.tf32.f32 "
        "{%0,%1,%2,%3}, {%4,%5,%6,%7}, {%8,%9}, {%0,%1,%2,%3};"
        : "+f"(c[0]), "+f"(c[1]), "+f"(c[2]), "+f"(c[3])
        : "r"(a[0]), "r"(a[1]), "r"(a[2]), "r"(a[3]), "r"(b[0]), "r"(b[1]));
}

__device__ __forceinline__ void cp16(uint32_t dst, const void* src, int sz) {
    asm volatile("cp.async.cg.shared.global [%0], [%1], 16, %2;"
        :: "r"(dst), "l"(src), "r"(sz) : "memory");
}

// ---------------- pipelined TF32 tensor-core GEMM ----------------------------
// C[M,N] = A[M,K] @ B[K,N] (+bias) (+res). A,B pre-rounded to tf32 values.
// CTA tile 128x128, 128 threads (4 warps, 2m x 2n), warp tile 64x64.
// BK=32, 3-stage cp.async pipeline; stage 35.8KB -> 2 CTAs/SM (dual-CTA
// overlap hides per-chunk syncs) while LDS:MMA ratio stays 1:1.
// A staged [m][k] stride 36 (bank 4g+tg); B staged [k][n] stride 136 (bank 8tg+g).
#define BM     128
#define BN     128
#define A_ST   36
#define B_ST   136
#define A_FL   (BM*A_ST)             // 4608 floats
#define B_FL   (32*B_ST)             // 4352 floats
#define ST_FL  (A_FL+B_FL)           // 8960 floats = 35840 B per stage
#define G_SMEM (3*ST_FL*4)           // 107520 bytes

__global__ __launch_bounds__(128) void ar_gemm_tf32(
    const float* __restrict__ A, const float* __restrict__ B,
    const float* __restrict__ bias, const float* __restrict__ res,
    float* __restrict__ C, int M, int N, int K)
{
    extern __shared__ float sm[];
    uint32_t sm_u = smem_u32(sm);

    int tid = threadIdx.x, lane = tid & 31, warp = tid >> 5;
    int wm = warp & 1, wn = warp >> 1;              // 2x2 warp grid, 64x64 each
    int bm = blockIdx.y * BM, bn = blockIdx.x * BN;
    int g = lane >> 2, tg = lane & 3;

    float acc[4][8][4];
    #pragma unroll
    for (int i = 0; i < 4; i++)
        #pragma unroll
        for (int j = 0; j < 8; j++)
            #pragma unroll
            for (int t = 0; t < 4; t++) acc[i][j][t] = 0.f;

    const int NC = K >> 5;

    auto load_chunk = [&](int cidx) {
        int s = cidx % 3, k0 = cidx << 5;
        uint32_t st = sm_u + (uint32_t)(s * ST_FL) * 4u;
        #pragma unroll
        for (int i = 0; i < 8; i++) {              // A: 1024 x 16B
            int idx = tid + (i << 7);
            int r = idx >> 3, cc = idx & 7;
            uint32_t dst = st + (uint32_t)(r * A_ST + cc * 4) * 4u;
            int gm = bm + r;
            bool v = (gm < M);
            const float* src = A + (size_t)(v ? gm : 0) * K + k0 + cc * 4;
            cp16(dst, src, v ? 16 : 0);
        }
        #pragma unroll
        for (int i = 0; i < 8; i++) {              // B: 1024 x 16B
            int idx = tid + (i << 7);
            int r = idx >> 5, cc = idx & 31;
            uint32_t dst = st + (uint32_t)(A_FL + r * B_ST + cc * 4) * 4u;
            const float* src = B + (size_t)(k0 + r) * N + bn + cc * 4;
            cp16(dst, src, 16);
        }
    };

    auto compute = [&](int s) {
        const float* Ab = sm + s * ST_FL;
        const float* Bb = Ab + A_FL;
        int m0 = wm * 64 + g;
        int n0 = wn * 64 + g;
        #pragma unroll
        for (int kb = 0; kb < 32; kb += 8) {
            uint32_t af[4][4];
            #pragma unroll
            for (int t = 0; t < 4; t++) {
                const float* ar0 = Ab + (m0 + t * 16) * A_ST + kb + tg;
                af[t][0] = __float_as_uint(ar0[0]);
                af[t][1] = __float_as_uint(ar0[8 * A_ST]);
                af[t][2] = __float_as_uint(ar0[4]);
                af[t][3] = __float_as_uint(ar0[8 * A_ST + 4]);
            }
            uint32_t bf[8][2];
            #pragma unroll
            for (int t = 0; t < 8; t++) {
                const float* br = Bb + (kb + tg) * B_ST + n0 + t * 8;
                bf[t][0] = __float_as_uint(br[0]);
                bf[t][1] = __float_as_uint(br[4 * B_ST]);
            }
            #pragma unroll
            for (int mt = 0; mt < 4; mt++)
                #pragma unroll
                for (int nt = 0; nt < 8; nt++)
                    mma_tf32(acc[mt][nt], af[mt], bf[nt]);
        }
    };

    load_chunk(0);
    asm volatile("cp.async.commit_group;" ::: "memory");
    load_chunk(1);
    asm volatile("cp.async.commit_group;" ::: "memory");
    load_chunk(2);
    asm volatile("cp.async.commit_group;" ::: "memory");

    for (int c = 0; c < NC; c++) {
        asm volatile("cp.async.wait_group 2;" ::: "memory");
        __syncthreads();
        compute(c % 3);
        __syncthreads();
        if (c + 3 < NC) load_chunk(c + 3);
        asm volatile("cp.async.commit_group;" ::: "memory");
    }

    // epilogue
    #pragma unroll
    for (int mt = 0; mt < 4; mt++) {
        int rbase = bm + wm * 64 + mt * 16 + g;
        #pragma unroll
        for (int half = 0; half < 2; half++) {
            int r = rbase + half * 8;
            if (r >= M) continue;
            #pragma unroll
            for (int nt = 0; nt < 8; nt++) {
                int cl = bn + wn * 64 + nt * 8 + 2 * tg;
                float2 v;
                v.x = acc[mt][nt][half * 2 + 0];
                v.y = acc[mt][nt][half * 2 + 1];
                if (bias) { v.x += bias[cl]; v.y += bias[cl + 1]; }
                if (res) {
                    float2 rr = *(const float2*)(res + (size_t)r * N + cl);
                    v.x += rr.x; v.y += rr.y;
                }
                *(float2*)(C + (size_t)r * N + cl) = v;
            }
        }
    }
}

// ---------------- vectorized tf32 round-copy ---------------------------------
__global__ void ar_round4(const float* __restrict__ in, float* __restrict__ out,
                          size_t n4) {
    size_t i = (size_t)blockIdx.x * blockDim.x + threadIdx.x;
    if (i < n4) {
        float4 v = ((const float4*)in)[i];
        v.x = rndf(v.x); v.y = rndf(v.y); v.z = rndf(v.z); v.w = rndf(v.w);
        ((float4*)out)[i] = v;
    }
}

// ---------------- reductions ------------------------------------------------
__device__ __forceinline__ float block_sum(float v, float* red) {
    int tid = threadIdx.x;
    #pragma unroll
    for (int o = 16; o > 0; o >>= 1) v += __shfl_xor_sync(0xffffffffu, v, o);
    if ((tid & 31) == 0) red[tid >> 5] = v;
    __syncthreads();
    if (tid == 0) {
        float s = red[0];
        int nw = blockDim.x >> 5;
        for (int i = 1; i < nw; i++) s += red[i];
        red[0] = s;
    }
    __syncthreads();
    float r = red[0];
    __syncthreads();
    return r;
}

__device__ __forceinline__ float block_max(float v, float* red) {
    int tid = threadIdx.x;
    #pragma unroll
    for (int o = 16; o > 0; o >>= 1) v = fmaxf(v, __shfl_xor_sync(0xffffffffu, v, o));
    if ((tid & 31) == 0) red[tid >> 5] = v;
    __syncthreads();
    if (tid == 0) {
        float s = red[0];
        int nw = blockDim.x >> 5;
        for (int i = 1; i < nw; i++) s = fmaxf(s, red[i]);
        red[0] = s;
    }
    __syncthreads();
    float r = red[0];
    __syncthreads();
    return r;
}

// ---------------- rope frequency table --------------------------------------
__global__ void ar_freqs(float* __restrict__ fc) {
    int t = blockIdx.x * blockDim.x + threadIdx.x;
    if (t >= SEQ * 32) return;
    int p = t >> 5, j = t & 31;
    float c = 0.f, s = 0.f;
    if (p > 0) {                       // cls token keeps cos=sin=0 (ref!)
        int pp = p - 1, yy = pp >> 4, xx = pp & 15;
        int i = j & 15;
        float fr = powf(10000.0f, -(float)i * (1.0f / 16.0f));
        float tt = (j < 16) ? (float)yy : (float)xx;
        float ang = tt * fr;
        c = cosf(ang); s = sinf(ang);
    }
    fc[2 * t] = c;
    fc[2 * t + 1] = s;
}

// ---------------- assemble (cond | patch) + pos + LayerNorm ------------------
__global__ __launch_bounds__(256) void ar_assemble_ln(
    const float* __restrict__ patch, const float* __restrict__ condr,
    const float* __restrict__ pos, const float* __restrict__ g,
    const float* __restrict__ bta, float* __restrict__ h)
{
    __shared__ float buf[EMBED];
    __shared__ float red[8];
    int m = blockIdx.x, tid = threadIdx.x;
    int b = m / SEQ, s = m % SEQ;
    const float* src = (s == 0) ? (condr + (size_t)b * EMBED)
                                : (patch + ((size_t)(b * 256 + s - 1)) * EMBED);
    float lsum = 0.f;
    for (int d = tid; d < EMBED; d += 256) {
        float v = src[d] + pos[(size_t)s * EMBED + d];
        buf[d] = v; lsum += v;
    }
    float mean = block_sum(lsum, red) * (1.f / EMBED);
    float ls2 = 0.f;
    for (int d = tid; d < EMBED; d += 256) {
        float dv = buf[d] - mean; ls2 += dv * dv;
    }
    float var = block_sum(ls2, red) * (1.f / EMBED);
    float rinv = rsqrtf(var + 1e-6f);
    for (int d = tid; d < EMBED; d += 256)
        h[(size_t)m * EMBED + d] = (buf[d] - mean) * rinv * g[d] + bta[d];
}

// ---------------- RMSNorm (tf32-rounded output: feeds GEMM A) ----------------
__global__ __launch_bounds__(256) void ar_rmsnorm(
    const float* __restrict__ x, const float* __restrict__ w, float* __restrict__ out)
{
    __shared__ float buf[EMBED];
    __shared__ float red[8];
    int m = blockIdx.x, tid = threadIdx.x;
    const float* xr = x + (size_t)m * EMBED;
    float ss = 0.f;
    for (int d = tid; d < EMBED; d += 256) {
        float v = xr[d]; buf[d] = v; ss += v * v;
    }
    ss = block_sum(ss, red);
    float r = rsqrtf(ss * (1.f / EMBED) + 1e-5f);
    for (int d = tid; d < EMBED; d += 256)
        out[(size_t)m * EMBED + d] = rndf(buf[d] * r * w[d]);
}

// ---------------- rope (in-place on q and k halves of qkv) -------------------
__global__ void ar_rope(float* __restrict__ qkv, const float* __restrict__ fc) {
    int t = blockIdx.x * blockDim.x + threadIdx.x;
    if (t >= MROWS * 512) return;
    int m = t >> 9, r = t & 511;
    int hh = r >> 5, j = r & 31;
    int s = m % SEQ;
    float c  = fc[(s * 32 + j) * 2];
    float sn = fc[(s * 32 + j) * 2 + 1];
    float* q = qkv + (size_t)m * (3 * EMBED) + hh * HD + 2 * j;
    float x0 = q[0], x1 = q[1];
    q[0] = x0 * c - x1 * sn;
    q[1] = x1 * c + x0 * sn;
    float* k = q + EMBED;
    x0 = k[0]; x1 = k[1];
    k[0] = x0 * c - x1 * sn;
    k[1] = x1 * c + x0 * sn;
}

// ---------------- attention: rows 0..255, whole K/V in smem -----------------
__device__ __forceinline__ void ar_attn_row(
    int qrow, int b, int h, const float* __restrict__ qkv,
    const float* __restrict__ Ks, const float* __restrict__ Vs,
    float* __restrict__ o)
{
    const float4* qp = (const float4*)(qkv + ((size_t)(b * SEQ + qrow)) * (3 * EMBED) + h * HD);
    float4 qv[16];
    #pragma unroll
    for (int i = 0; i < 16; i++) qv[i] = qp[i];
    float acc[64];
    #pragma unroll
    for (int d = 0; d < 64; d++) acc[d] = 0.f;
    float mx = -1e30f, l = 0.f;
    for (int j = 0; j <= qrow; j++) {
        const float4* kr = (const float4*)(Ks + j * 64);
        float s0 = 0.f, s1 = 0.f, s2 = 0.f, s3 = 0.f;
        #pragma unroll
        for (int i = 0; i < 16; i++) {
            float4 kk = kr[i];
            s0 = fmaf(qv[i].x, kk.x, s0);
            s1 = fmaf(qv[i].y, kk.y, s1);
            s2 = fmaf(qv[i].z, kk.z, s2);
            s3 = fmaf(qv[i].w, kk.w, s3);
        }
        float s = ((s0 + s1) + (s2 + s3)) * 0.125f;
        float nm = fmaxf(mx, s);
        float corr = __expf(mx - nm);
        float p = __expf(s - nm);
        l = l * corr + p;
        const float4* vr = (const float4*)(Vs + j * 64);
        #pragma unroll
        for (int i = 0; i < 16; i++) {
            float4 vv = vr[i];
            acc[4*i+0] = fmaf(acc[4*i+0], corr, p * vv.x);
            acc[4*i+1] = fmaf(acc[4*i+1], corr, p * vv.y);
            acc[4*i+2] = fmaf(acc[4*i+2], corr, p * vv.z);
            acc[4*i+3] = fmaf(acc[4*i+3], corr, p * vv.w);
        }
        mx = nm;
    }
    float inv = 1.f / l;
    float* op = o + ((size_t)(b * SEQ + qrow)) * EMBED + h * HD;
    #pragma unroll
    for (int d = 0; d < 64; d++) op[d] = rndf(acc[d] * inv);
}

__global__ __launch_bounds__(128) void ar_attn(const float* __restrict__ qkv,
                                               float* __restrict__ o)
{
    extern __shared__ float smkv[];
    float* Ks = smkv;
    float* Vs = smkv + SEQ * 64;
    int h = blockIdx.x, b = blockIdx.y, tid = threadIdx.x;
    const float* base = qkv + (size_t)b * SEQ * (3 * EMBED) + EMBED + h * HD;
    for (int idx = tid; idx < SEQ * 16; idx += 128) {
        int s = idx >> 4, c = idx & 15;
        *(float4*)(Ks + s * 64 + c * 4) = *(const float4*)(base + (size_t)s * (3 * EMBED) + c * 4);
        *(float4*)(Vs + s * 64 + c * 4) = *(const float4*)(base + EMBED + (size_t)s * (3 * EMBED) + c * 4);
    }
    __syncthreads();
    ar_attn_row(tid, b, h, qkv, Ks, Vs, o);
    ar_attn_row(255 - tid, b, h, qkv, Ks, Vs, o);
}

// ---------------- attention row 256 (longest row, j-parallel) ---------------
__global__ __launch_bounds__(256) void ar_attn_last(const float* __restrict__ qkv,
                                                    float* __restrict__ o)
{
    __shared__ float qs[64];
    __shared__ float sc[SEQ];
    __shared__ float red[8];
    __shared__ float part[4][64];
    int h = blockIdx.x, b = blockIdx.y, tid = threadIdx.x;
    const float* qrow = qkv + ((size_t)(b * SEQ + 256)) * (3 * EMBED) + h * HD;
    if (tid < 64) qs[tid] = qrow[tid];
    __syncthreads();
    const float* kbase = qkv + (size_t)b * SEQ * (3 * EMBED) + EMBED + (size_t)h * HD;
    float lm = -1e30f;
    for (int j = tid; j < SEQ; j += 256) {
        const float* kr = kbase + (size_t)j * (3 * EMBED);
        float s = 0.f;
        #pragma unroll
        for (int d = 0; d < 64; d++) s = fmaf(qs[d], kr[d], s);
        s *= 0.125f;
        sc[j] = s;
        lm = fmaxf(lm, s);
    }
    float M = block_max(lm, red);
    float ls = 0.f;
    for (int j = tid; j < SEQ; j += 256) {
        float p = __expf(sc[j] - M);
        sc[j] = p;
        ls += p;
    }
    float L = block_sum(ls, red);
    int d = tid & 63, c = tid >> 6;
    const float* vbase = kbase + EMBED;
    float a = 0.f;
    for (int j = c; j < SEQ; j += 4)
        a = fmaf(sc[j], vbase[(size_t)j * (3 * EMBED) + d], a);
    part[c][d] = a;
    __syncthreads();
    if (tid < 64) {
        float s = part[0][tid] + part[1][tid] + part[2][tid] + part[3][tid];
        o[((size_t)(b * SEQ + 256)) * EMBED + h * HD + tid] = rndf(s / L);
    }
}

// ---------------- fused silu(u) * v (rounded: feeds GEMM A) -----------------
__global__ void ar_silu_mul(float* __restrict__ u, const float* __restrict__ v, int n) {
    int i = blockIdx.x * blockDim.x + threadIdx.x;
    if (i < n) {
        float uu = u[i];
        float s = uu / (1.f + __expf(-uu));
        u[i] = rndf(s * v[i]);
    }
}

// ---------------- host orchestration ----------------------------------------
static inline void launch_gemm(const float* A, const float* B, const float* bias,
                               const float* res, float* C, int M, int N, int K) {
    dim3 grid(N / BN, (M + BM - 1) / BM);
    ar_gemm_tf32<<<grid, 128, G_SMEM>>>(A, B, bias, res, C, M, N, K);
}

static inline void launch_round(const float* in, float* out, size_t n) {
    size_t n4 = n / 4;
    ar_round4<<<(unsigned)((n4 + 255) / 256), 256>>>(in, out, n4);
}

extern "C" void kernel_launch(void* const* d_in, const int* in_sizes, int n_in,
                              void* d_out, int out_size)
{
    const float* x       = (const float*)d_in[0];
    const float* cond    = (const float*)d_in[1];
    const float* patch_w = (const float*)d_in[2];
    const float* patch_b = (const float*)d_in[3];
    const float* ln_g    = (const float*)d_in[4];
    const float* ln_b    = (const float*)d_in[5];
    const float* pos     = (const float*)d_in[6];
    const float* cond_w  = (const float*)d_in[7];
    const float* cond_b  = (const float*)d_in[8];
    const float* wqkv    = (const float*)d_in[9];
    const float* wo      = (const float*)d_in[10];
    const float* w1      = (const float*)d_in[11];
    const float* w2      = (const float*)d_in[12];
    const float* w3      = (const float*)d_in[13];
    const float* anw     = (const float*)d_in[14];
    const float* fnw     = (const float*)d_in[15];
    float* h = (float*)d_out;

    float *pa, *pqkv, *po, *pu, *pfc, *pxr, *pcr, *pwt;
    cudaGetSymbolAddress((void**)&pa,   g_a);
    cudaGetSymbolAddress((void**)&pqkv, g_qkv);
    cudaGetSymbolAddress((void**)&po,   g_o);
    cudaGetSymbolAddress((void**)&pu,   g_u);
    cudaGetSymbolAddress((void**)&pfc,  g_fc);
    cudaGetSymbolAddress((void**)&pxr,  g_xr);
    cudaGetSymbolAddress((void**)&pcr,  g_cr);
    cudaGetSymbolAddress((void**)&pwt,  g_wt);

    cudaFuncSetAttribute(ar_attn, cudaFuncAttributeMaxDynamicSharedMemorySize,
                         SEQ * 64 * 2 * (int)sizeof(float));
    cudaFuncSetAttribute(ar_gemm_tf32, cudaFuncAttributeMaxDynamicSharedMemorySize,
                         G_SMEM);

    float* qkvR   = pwt + OFF_QKV;
    float* woR    = pwt + OFF_WO;
    float* w1R    = pwt + OFF_W1;
    float* w3R    = pwt + OFF_W3;
    float* w2R    = pwt + OFF_W2;
    float* patchR = pwt + OFF_PATCH;
    float* condR  = pwt + OFF_COND;

    // tf32 round-copy all weights + A-side raw inputs (once per launch)
    launch_round(wqkv,    qkvR,   (size_t)NB * 1024 * 3072);
    launch_round(wo,      woR,    (size_t)NB * 1024 * 1024);
    launch_round(w1,      w1R,    (size_t)NB * 1024 * HIDDEN);
    launch_round(w3,      w3R,    (size_t)NB * 1024 * HIDDEN);
    launch_round(w2,      w2R,    (size_t)NB * HIDDEN * 1024);
    launch_round(patch_w, patchR, (size_t)768 * 1024);
    launch_round(cond_w,  condR,  (size_t)1024 * 1024);
    launch_round(x,       pxr,    (size_t)8192 * 768);
    launch_round(cond,    pcr,    (size_t)32 * 1024);

    // rope table
    ar_freqs<<<(SEQ * 32 + 255) / 256, 256>>>(pfc);
    // patch embed -> g_a ; cond embed -> g_o
    launch_gemm(pxr, patchR, patch_b, nullptr, pa, BATCH * 256, EMBED, 768);
    launch_gemm(pcr, condR, cond_b, nullptr, po, BATCH, EMBED, EMBED);
    // assemble + pos + layernorm -> h (d_out)
    ar_assemble_ln<<<MROWS, 256>>>(pa, po, pos, ln_g, ln_b, h);

    for (int l = 0; l < NB; l++) {
        float* qkv_l = qkvR + (size_t)l * 1024 * 3072;
        float* wo_l  = woR  + (size_t)l * 1024 * 1024;
        float* w1_l  = w1R  + (size_t)l * 1024 * HIDDEN;
        float* w3_l  = w3R  + (size_t)l * 1024 * HIDDEN;
        float* w2_l  = w2R  + (size_t)l * HIDDEN * 1024;

        ar_rmsnorm<<<MROWS, 256>>>(h, anw + (size_t)l * EMBED, pa);
        launch_gemm(pa, qkv_l, nullptr, nullptr, pqkv, MROWS, 3 * EMBED, EMBED);
        ar_rope<<<(MROWS * 512 + 255) / 256, 256>>>(pqkv, pfc);
        ar_attn<<<dim3(HEADS, BATCH), 128, SEQ * 64 * 2 * (int)sizeof(float)>>>(pqkv, po);
        ar_attn_last<<<dim3(HEADS, BATCH), 256>>>(pqkv, po);
        launch_gemm(po, wo_l, nullptr, h, h, MROWS, EMBED, EMBED);

        ar_rmsnorm<<<MROWS, 256>>>(h, fnw + (size_t)l * EMBED, pa);
        launch_gemm(pa, w1_l, nullptr, nullptr, pu, MROWS, HIDDEN, EMBED);
        launch_gemm(pa, w3_l, nullptr, nullptr, pqkv, MROWS, HIDDEN, EMBED);
        ar_silu_mul<<<(MROWS * HIDDEN + 255) / 256, 256>>>(pu, pqkv, MROWS * HIDDEN);
        launch_gemm(pu, w2_l, nullptr, h, h, MROWS, EMBED, HIDDEN);
    }
}

// round 10
// speedup vs baseline: 1.5862x; 1.5232x over previous
#include <cuda_runtime.h>
#include <cuda_fp16.h>
#include <math.h>
#include <stdint.h>

#define EMBED   1024
#define HEADS   16
#define HD      64
#define NB      12
#define SEQ     257
#define BATCH   32
#define MROWS   (BATCH*SEQ)      // 8224
#define HIDDEN  2816

// ---------------- scratch (device globals; no allocations allowed) ----------
__device__ __align__(256) __half g_a[MROWS*EMBED];      // rmsnorm out (half, GEMM A)
__device__ __align__(256) __half g_o[MROWS*EMBED];      // attn out (half, GEMM A)
__device__ __align__(256) __half g_u[MROWS*HIDDEN];     // silu(u)*v (half, GEMM A)
__device__ __align__(256) __half g_xh[8192*768];        // x (half)
__device__ __align__(256) __half g_ch[32*1024];         // cond (half)
__device__ __align__(256) float  g_qkv[MROWS*3*EMBED];  // qkv / w3-out / cond-out (f32)
__device__ __align__(256) float  g_f1[MROWS*HIDDEN];    // w1-out / patch-out (f32)
__device__ __align__(256) float  g_fc[SEQ*32*2];        // rope cos/sin table

// half weights, k-pair interleaved: [K/2][N] half2
#define OFF_QKV   ((size_t)0)
#define OFF_WO    (OFF_QKV + (size_t)NB*1024*3072)
#define OFF_W1    (OFF_WO  + (size_t)NB*1024*1024)
#define OFF_W3    (OFF_W1  + (size_t)NB*1024*HIDDEN)
#define OFF_W2    (OFF_W3  + (size_t)NB*1024*HIDDEN)
#define OFF_PATCH (OFF_W2  + (size_t)NB*HIDDEN*1024)
#define OFF_COND  (OFF_PATCH + (size_t)768*1024)
#define WT_TOTAL  (OFF_COND + (size_t)1024*1024)
__device__ __align__(256) __half g_wt[WT_TOTAL];

// ---------------- helpers ----------------------------------------------------
__device__ __forceinline__ uint32_t smem_u32(const void* p) {
    uint32_t a;
    asm("{ .reg .u64 t; cvta.to.shared.u64 t, %1; cvt.u32.u64 %0, t; }" : "=r"(a) : "l"(p));
    return a;
}

__device__ __forceinline__ void mma_f16(float c[4], const uint32_t a[4],
                                        const uint32_t b[2]) {
    asm volatile(
        "mma.sync.aligned.m16n8k16.row.col.f32.f16.f16.f32 "
        "{%0,%1,%2,%3}, {%4,%5,%6,%7}, {%8,%9}, {%0,%1,%2,%3};"
        : "+f"(c[0]), "+f"(c[1]), "+f"(c[2]), "+f"(c[3])
        : "r"(a[0]), "r"(a[1]), "r"(a[2]), "r"(a[3]), "r"(b[0]), "r"(b[1]));
}

__device__ __forceinline__ void cp16(uint32_t dst, const void* src, int sz) {
    asm volatile("cp.async.cg.shared.global [%0], [%1], 16, %2;"
        :: "r"(dst), "l"(src), "r"(sz) : "memory");
}

// ---------------- pipelined FP16 tensor-core GEMM ----------------------------
// C[M,N](f32) = A[M,K](f16) @ B[K,N](f16, k-pair interleaved) (+bias)(+res).
// CTA tile 128x128, 128 threads (2x2 warps of 64x64), BK=64 (4 x k16 steps),
// 3-stage cp.async pipeline, 2 CTAs/SM.
// A smem: [128 rows][36 words] (72 halfs: 64 data + 8 pad); bank = 4g+tg (bijective)
// B smem: [32 k2-rows][136 words] (128 half2 + 8 pad);     bank = 8tg+g (bijective)
#define BM     128
#define BN     128
#define BK     64
#define A_SW   36
#define B_SW   136
#define A_WORDS (BM*A_SW)            // 4608
#define B_WORDS ((BK/2)*B_SW)        // 4352
#define ST_WORDS (A_WORDS+B_WORDS)   // 8960 words = 35840 B/stage
#define G_SMEM (3*ST_WORDS*4)        // 107520 B

__global__ __launch_bounds__(128) void ar_gemm_f16(
    const __half* __restrict__ A, const __half2* __restrict__ B2,
    const float* __restrict__ bias, const float* __restrict__ res,
    float* __restrict__ C, int M, int N, int K)
{
    extern __shared__ uint32_t sm[];
    uint32_t sm_u = smem_u32(sm);

    int tid = threadIdx.x, lane = tid & 31, warp = tid >> 5;
    int wm = warp & 1, wn = warp >> 1;              // 2x2 warp grid, 64x64 each
    int bm = blockIdx.y * BM, bn = blockIdx.x * BN;
    int g = lane >> 2, tg = lane & 3;

    float acc[4][8][4];
    #pragma unroll
    for (int i = 0; i < 4; i++)
        #pragma unroll
        for (int j = 0; j < 8; j++)
            #pragma unroll
            for (int t = 0; t < 4; t++) acc[i][j][t] = 0.f;

    const int NC = K / BK;

    auto load_chunk = [&](int cidx) {
        int s = cidx % 3;
        int k0 = cidx * BK;                        // in halfs
        uint32_t st = sm_u + (uint32_t)(s * ST_WORDS) * 4u;
        #pragma unroll
        for (int i = 0; i < 8; i++) {              // A: 128 rows x 8 cp16
            int idx = tid + (i << 7);
            int r = idx >> 3, cc = idx & 7;
            uint32_t dst = st + (uint32_t)(r * A_SW + cc * 4) * 4u;
            int gm = bm + r;
            bool v = (gm < M);
            const __half* src = A + (size_t)(v ? gm : 0) * K + k0 + cc * 8;
            cp16(dst, src, v ? 16 : 0);
        }
        #pragma unroll
        for (int i = 0; i < 8; i++) {              // B: 32 k2-rows x 32 cp16
            int idx = tid + (i << 7);
            int r = idx >> 5, cc = idx & 31;
            uint32_t dst = st + (uint32_t)(A_WORDS + r * B_SW + cc * 4) * 4u;
            const __half2* src = B2 + (size_t)(k0 / 2 + r) * N + bn + cc * 4;
            cp16(dst, src, 16);
        }
    };

    auto compute = [&](int s) {
        const uint32_t* St = sm + s * ST_WORDS;
        const uint32_t* Ab = St;
        const uint32_t* Bb = St + A_WORDS;
        int m0 = wm * 64 + g;
        int n0 = wn * 64 + g;
        #pragma unroll
        for (int ks = 0; ks < 4; ks++) {           // 4 k16 steps
            int kw = ks * 8;                        // word offset (= 16 halfs)
            uint32_t af[4][4];
            #pragma unroll
            for (int mt = 0; mt < 4; mt++) {
                int base = (m0 + mt * 16) * A_SW + kw + tg;
                af[mt][0] = Ab[base];
                af[mt][1] = Ab[base + 8 * A_SW];
                af[mt][2] = Ab[base + 4];
                af[mt][3] = Ab[base + 8 * A_SW + 4];
            }
            uint32_t bf[8][2];
            #pragma unroll
            for (int nt = 0; nt < 8; nt++) {
                int bb = (kw + tg) * B_SW + n0 + nt * 8;
                bf[nt][0] = Bb[bb];
                bf[nt][1] = Bb[bb + 4 * B_SW];
            }
            #pragma unroll
            for (int mt = 0; mt < 4; mt++)
                #pragma unroll
                for (int nt = 0; nt < 8; nt++)
                    mma_f16(acc[mt][nt], af[mt], bf[nt]);
        }
    };

    load_chunk(0);
    asm volatile("cp.async.commit_group;" ::: "memory");
    load_chunk(1);
    asm volatile("cp.async.commit_group;" ::: "memory");
    load_chunk(2);
    asm volatile("cp.async.commit_group;" ::: "memory");

    for (int c = 0; c < NC; c++) {
        asm volatile("cp.async.wait_group 2;" ::: "memory");
        __syncthreads();
        compute(c % 3);
        __syncthreads();
        if (c + 3 < NC) load_chunk(c + 3);
        asm volatile("cp.async.commit_group;" ::: "memory");
    }

    // epilogue (c0,c1 -> row g; c2,c3 -> row g+8; cols 2tg,2tg+1)
    #pragma unroll
    for (int mt = 0; mt < 4; mt++) {
        int rbase = bm + wm * 64 + mt * 16 + g;
        #pragma unroll
        for (int half = 0; half < 2; half++) {
            int r = rbase + half * 8;
            if (r >= M) continue;
            #pragma unroll
            for (int nt = 0; nt < 8; nt++) {
                int cl = bn + wn * 64 + nt * 8 + 2 * tg;
                float2 v;
                v.x = acc[mt][nt][half * 2 + 0];
                v.y = acc[mt][nt][half * 2 + 1];
                if (bias) { v.x += bias[cl]; v.y += bias[cl + 1]; }
                if (res) {
                    float2 rr = *(const float2*)(res + (size_t)r * N + cl);
                    v.x += rr.x; v.y += rr.y;
                }
                *(float2*)(C + (size_t)r * N + cl) = v;
            }
        }
    }
}

// ---------------- weight convert: [K][N] f32 -> [K/2][N] half2 ---------------
__global__ __launch_bounds__(256) void ar_b2h(const float* __restrict__ in,
                                              __half2* __restrict__ out,
                                              int K, int N) {
    size_t z = blockIdx.z;
    in  += z * (size_t)K * N;
    out += z * (size_t)(K / 2) * N;
    int total = (K / 2) * N;
    int idx = blockIdx.x * blockDim.x + threadIdx.x;
    if (idx >= total) return;
    int k2 = idx / N, n = idx - k2 * N;
    float lo = in[(size_t)(2 * k2) * N + n];
    float hi = in[(size_t)(2 * k2 + 1) * N + n];
    out[idx] = __floats2half2_rn(lo, hi);
}

// ---------------- activation convert: f32 -> f16 flat ------------------------
__global__ void ar_f2h(const float* __restrict__ in, __half2* __restrict__ out,
                       size_t n4) {
    size_t i = (size_t)blockIdx.x * blockDim.x + threadIdx.x;
    if (i < n4) {
        float4 v = ((const float4*)in)[i];
        out[2 * i]     = __floats2half2_rn(v.x, v.y);
        out[2 * i + 1] = __floats2half2_rn(v.z, v.w);
    }
}

// ---------------- reductions ------------------------------------------------
__device__ __forceinline__ float block_sum(float v, float* red) {
    int tid = threadIdx.x;
    #pragma unroll
    for (int o = 16; o > 0; o >>= 1) v += __shfl_xor_sync(0xffffffffu, v, o);
    if ((tid & 31) == 0) red[tid >> 5] = v;
    __syncthreads();
    if (tid == 0) {
        float s = red[0];
        int nw = blockDim.x >> 5;
        for (int i = 1; i < nw; i++) s += red[i];
        red[0] = s;
    }
    __syncthreads();
    float r = red[0];
    __syncthreads();
    return r;
}

__device__ __forceinline__ float block_max(float v, float* red) {
    int tid = threadIdx.x;
    #pragma unroll
    for (int o = 16; o > 0; o >>= 1) v = fmaxf(v, __shfl_xor_sync(0xffffffffu, v, o));
    if ((tid & 31) == 0) red[tid >> 5] = v;
    __syncthreads();
    if (tid == 0) {
        float s = red[0];
        int nw = blockDim.x >> 5;
        for (int i = 1; i < nw; i++) s = fmaxf(s, red[i]);
        red[0] = s;
    }
    __syncthreads();
    float r = red[0];
    __syncthreads();
    return r;
}

// ---------------- rope frequency table --------------------------------------
__global__ void ar_freqs(float* __restrict__ fc) {
    int t = blockIdx.x * blockDim.x + threadIdx.x;
    if (t >= SEQ * 32) return;
    int p = t >> 5, j = t & 31;
    float c = 0.f, s = 0.f;
    if (p > 0) {                       // cls token keeps cos=sin=0 (ref!)
        int pp = p - 1, yy = pp >> 4, xx = pp & 15;
        int i = j & 15;
        float fr = powf(10000.0f, -(float)i * (1.0f / 16.0f));
        float tt = (j < 16) ? (float)yy : (float)xx;
        float ang = tt * fr;
        c = cosf(ang); s = sinf(ang);
    }
    fc[2 * t] = c;
    fc[2 * t + 1] = s;
}

// ---------------- assemble (cond | patch) + pos + LayerNorm ------------------
__global__ __launch_bounds__(256) void ar_assemble_ln(
    const float* __restrict__ patch, const float* __restrict__ condr,
    const float* __restrict__ pos, const float* __restrict__ g,
    const float* __restrict__ bta, float* __restrict__ h)
{
    __shared__ float buf[EMBED];
    __shared__ float red[8];
    int m = blockIdx.x, tid = threadIdx.x;
    int b = m / SEQ, s = m % SEQ;
    const float* src = (s == 0) ? (condr + (size_t)b * EMBED)
                                : (patch + ((size_t)(b * 256 + s - 1)) * EMBED);
    float lsum = 0.f;
    for (int d = tid; d < EMBED; d += 256) {
        float v = src[d] + pos[(size_t)s * EMBED + d];
        buf[d] = v; lsum += v;
    }
    float mean = block_sum(lsum, red) * (1.f / EMBED);
    float ls2 = 0.f;
    for (int d = tid; d < EMBED; d += 256) {
        float dv = buf[d] - mean; ls2 += dv * dv;
    }
    float var = block_sum(ls2, red) * (1.f / EMBED);
    float rinv = rsqrtf(var + 1e-6f);
    for (int d = tid; d < EMBED; d += 256)
        h[(size_t)m * EMBED + d] = (buf[d] - mean) * rinv * g[d] + bta[d];
}

// ---------------- RMSNorm (half output: feeds GEMM A) ------------------------
__global__ __launch_bounds__(256) void ar_rmsnorm(
    const float* __restrict__ x, const float* __restrict__ w, __half* __restrict__ out)
{
    __shared__ float buf[EMBED];
    __shared__ float red[8];
    int m = blockIdx.x, tid = threadIdx.x;
    const float* xr = x + (size_t)m * EMBED;
    float ss = 0.f;
    for (int d = tid; d < EMBED; d += 256) {
        float v = xr[d]; buf[d] = v; ss += v * v;
    }
    ss = block_sum(ss, red);
    float r = rsqrtf(ss * (1.f / EMBED) + 1e-5f);
    __half2* o2 = (__half2*)(out + (size_t)m * EMBED);
    for (int d2 = tid; d2 < EMBED / 2; d2 += 256)
        o2[d2] = __floats2half2_rn(buf[2 * d2] * r * w[2 * d2],
                                   buf[2 * d2 + 1] * r * w[2 * d2 + 1]);
}

// ---------------- rope (in-place on q and k halves of qkv) -------------------
__global__ void ar_rope(float* __restrict__ qkv, const float* __restrict__ fc) {
    int t = blockIdx.x * blockDim.x + threadIdx.x;
    if (t >= MROWS * 512) return;
    int m = t >> 9, r = t & 511;
    int hh = r >> 5, j = r & 31;
    int s = m % SEQ;
    float c  = fc[(s * 32 + j) * 2];
    float sn = fc[(s * 32 + j) * 2 + 1];
    float* q = qkv + (size_t)m * (3 * EMBED) + hh * HD + 2 * j;
    float x0 = q[0], x1 = q[1];
    q[0] = x0 * c - x1 * sn;
    q[1] = x1 * c + x0 * sn;
    float* k = q + EMBED;
    x0 = k[0]; x1 = k[1];
    k[0] = x0 * c - x1 * sn;
    k[1] = x1 * c + x0 * sn;
}

// ---------------- attention: rows 0..255, whole K/V in smem -----------------
__device__ __forceinline__ void ar_attn_row(
    int qrow, int b, int h, const float* __restrict__ qkv,
    const float* __restrict__ Ks, const float* __restrict__ Vs,
    __half* __restrict__ o)
{
    const float4* qp = (const float4*)(qkv + ((size_t)(b * SEQ + qrow)) * (3 * EMBED) + h * HD);
    float4 qv[16];
    #pragma unroll
    for (int i = 0; i < 16; i++) qv[i] = qp[i];
    float acc[64];
    #pragma unroll
    for (int d = 0; d < 64; d++) acc[d] = 0.f;
    float mx = -1e30f, l = 0.f;
    for (int j = 0; j <= qrow; j++) {
        const float4* kr = (const float4*)(Ks + j * 64);
        float s0 = 0.f, s1 = 0.f, s2 = 0.f, s3 = 0.f;
        #pragma unroll
        for (int i = 0; i < 16; i++) {
            float4 kk = kr[i];
            s0 = fmaf(qv[i].x, kk.x, s0);
            s1 = fmaf(qv[i].y, kk.y, s1);
            s2 = fmaf(qv[i].z, kk.z, s2);
            s3 = fmaf(qv[i].w, kk.w, s3);
        }
        float s = ((s0 + s1) + (s2 + s3)) * 0.125f;
        float nm = fmaxf(mx, s);
        float corr = __expf(mx - nm);
        float p = __expf(s - nm);
        l = l * corr + p;
        const float4* vr = (const float4*)(Vs + j * 64);
        #pragma unroll
        for (int i = 0; i < 16; i++) {
            float4 vv = vr[i];
            acc[4*i+0] = fmaf(acc[4*i+0], corr, p * vv.x);
            acc[4*i+1] = fmaf(acc[4*i+1], corr, p * vv.y);
            acc[4*i+2] = fmaf(acc[4*i+2], corr, p * vv.z);
            acc[4*i+3] = fmaf(acc[4*i+3], corr, p * vv.w);
        }
        mx = nm;
    }
    float inv = 1.f / l;
    __half2* op = (__half2*)(o + ((size_t)(b * SEQ + qrow)) * EMBED + h * HD);
    #pragma unroll
    for (int d = 0; d < 32; d++)
        op[d] = __floats2half2_rn(acc[2 * d] * inv, acc[2 * d + 1] * inv);
}

__global__ __launch_bounds__(128) void ar_attn(const float* __restrict__ qkv,
                                               __half* __restrict__ o)
{
    extern __shared__ float smkv[];
    float* Ks = smkv;
    float* Vs = smkv + SEQ * 64;
    int h = blockIdx.x, b = blockIdx.y, tid = threadIdx.x;
    const float* base = qkv + (size_t)b * SEQ * (3 * EMBED) + EMBED + h * HD;
    for (int idx = tid; idx < SEQ * 16; idx += 128) {
        int s = idx >> 4, c = idx & 15;
        *(float4*)(Ks + s * 64 + c * 4) = *(const float4*)(base + (size_t)s * (3 * EMBED) + c * 4);
        *(float4*)(Vs + s * 64 + c * 4) = *(const float4*)(base + EMBED + (size_t)s * (3 * EMBED) + c * 4);
    }
    __syncthreads();
    ar_attn_row(tid, b, h, qkv, Ks, Vs, o);
    ar_attn_row(255 - tid, b, h, qkv, Ks, Vs, o);
}

// ---------------- attention row 256 (longest row, j-parallel) ---------------
__global__ __launch_bounds__(256) void ar_attn_last(const float* __restrict__ qkv,
                                                    __half* __restrict__ o)
{
    __shared__ float qs[64];
    __shared__ float sc[SEQ];
    __shared__ float red[8];
    __shared__ float part[4][64];
    int h = blockIdx.x, b = blockIdx.y, tid = threadIdx.x;
    const float* qrow = qkv + ((size_t)(b * SEQ + 256)) * (3 * EMBED) + h * HD;
    if (tid < 64) qs[tid] = qrow[tid];
    __syncthreads();
    const float* kbase = qkv + (size_t)b * SEQ * (3 * EMBED) + EMBED + (size_t)h * HD;
    float lm = -1e30f;
    for (int j = tid; j < SEQ; j += 256) {
        const float* kr = kbase + (size_t)j * (3 * EMBED);
        float s = 0.f;
        #pragma unroll
        for (int d = 0; d < 64; d++) s = fmaf(qs[d], kr[d], s);
        s *= 0.125f;
        sc[j] = s;
        lm = fmaxf(lm, s);
    }
    float M = block_max(lm, red);
    float ls = 0.f;
    for (int j = tid; j < SEQ; j += 256) {
        float p = __expf(sc[j] - M);
        sc[j] = p;
        ls += p;
    }
    float L = block_sum(ls, red);
    int d = tid & 63, c = tid >> 6;
    const float* vbase = kbase + EMBED;
    float a = 0.f;
    for (int j = c; j < SEQ; j += 4)
        a = fmaf(sc[j], vbase[(size_t)j * (3 * EMBED) + d], a);
    part[c][d] = a;
    __syncthreads();
    if (tid < 64) {
        float s = part[0][tid] + part[1][tid] + part[2][tid] + part[3][tid];
        o[((size_t)(b * SEQ + 256)) * EMBED + h * HD + tid] = __float2half(s / L);
    }
}

// ---------------- fused silu(u) * v (half out: feeds GEMM A) -----------------
__global__ void ar_silu_mul(const float* __restrict__ u, const float* __restrict__ v,
                            __half2* __restrict__ out, int n2) {
    int i = blockIdx.x * blockDim.x + threadIdx.x;
    if (i < n2) {
        float2 uu = ((const float2*)u)[i];
        float2 vv = ((const float2*)v)[i];
        float s0 = uu.x / (1.f + __expf(-uu.x)) * vv.x;
        float s1 = uu.y / (1.f + __expf(-uu.y)) * vv.y;
        out[i] = __floats2half2_rn(s0, s1);
    }
}

// ---------------- host orchestration ----------------------------------------
static inline void launch_gemm(const __half* A, const __half* B, const float* bias,
                               const float* res, float* C, int M, int N, int K) {
    dim3 grid(N / BN, (M + BM - 1) / BM);
    ar_gemm_f16<<<grid, 128, G_SMEM>>>(A, (const __half2*)B, bias, res, C, M, N, K);
}

static inline void launch_b2h(const float* in, __half* out, int K, int N, int L) {
    int total = (K / 2) * N;
    ar_b2h<<<dim3((total + 255) / 256, 1, L), 256>>>(in, (__half2*)out, K, N);
}

static inline void launch_f2h(const float* in, __half* out, size_t n) {
    size_t n4 = n / 4;
    ar_f2h<<<(unsigned)((n4 + 255) / 256), 256>>>(in, (__half2*)out, n4);
}

extern "C" void kernel_launch(void* const* d_in, const int* in_sizes, int n_in,
                              void* d_out, int out_size)
{
    const float* x       = (const float*)d_in[0];
    const float* cond    = (const float*)d_in[1];
    const float* patch_w = (const float*)d_in[2];
    const float* patch_b = (const float*)d_in[3];
    const float* ln_g    = (const float*)d_in[4];
    const float* ln_b    = (const float*)d_in[5];
    const float* pos     = (const float*)d_in[6];
    const float* cond_w  = (const float*)d_in[7];
    const float* cond_b  = (const float*)d_in[8];
    const float* wqkv    = (const float*)d_in[9];
    const float* wo      = (const float*)d_in[10];
    const float* w1      = (const float*)d_in[11];
    const float* w2      = (const float*)d_in[12];
    const float* w3      = (const float*)d_in[13];
    const float* anw     = (const float*)d_in[14];
    const float* fnw     = (const float*)d_in[15];
    float* h = (float*)d_out;

    __half *pa, *po, *pu, *pxh, *pch, *pwt;
    float *pqkv, *pf1, *pfc;
    cudaGetSymbolAddress((void**)&pa,   g_a);
    cudaGetSymbolAddress((void**)&po,   g_o);
    cudaGetSymbolAddress((void**)&pu,   g_u);
    cudaGetSymbolAddress((void**)&pxh,  g_xh);
    cudaGetSymbolAddress((void**)&pch,  g_ch);
    cudaGetSymbolAddress((void**)&pwt,  g_wt);
    cudaGetSymbolAddress((void**)&pqkv, g_qkv);
    cudaGetSymbolAddress((void**)&pf1,  g_f1);
    cudaGetSymbolAddress((void**)&pfc,  g_fc);

    cudaFuncSetAttribute(ar_attn, cudaFuncAttributeMaxDynamicSharedMemorySize,
                         SEQ * 64 * 2 * (int)sizeof(float));
    cudaFuncSetAttribute(ar_gemm_f16, cudaFuncAttributeMaxDynamicSharedMemorySize,
                         G_SMEM);

    __half* qkvH   = pwt + OFF_QKV;
    __half* woH    = pwt + OFF_WO;
    __half* w1H    = pwt + OFF_W1;
    __half* w3H    = pwt + OFF_W3;
    __half* w2H    = pwt + OFF_W2;
    __half* patchH = pwt + OFF_PATCH;
    __half* condH  = pwt + OFF_COND;

    // convert weights (k-pair interleaved) + A-side raw inputs to half
    launch_b2h(wqkv,    qkvH,   1024, 3072, NB);
    launch_b2h(wo,      woH,    1024, 1024, NB);
    launch_b2h(w1,      w1H,    1024, HIDDEN, NB);
    launch_b2h(w3,      w3H,    1024, HIDDEN, NB);
    launch_b2h(w2,      w2H,    HIDDEN, 1024, NB);
    launch_b2h(patch_w, patchH, 768, 1024, 1);
    launch_b2h(cond_w,  condH,  1024, 1024, 1);
    launch_f2h(x,    pxh, (size_t)8192 * 768);
    launch_f2h(cond, pch, (size_t)32 * 1024);

    // rope table
    ar_freqs<<<(SEQ * 32 + 255) / 256, 256>>>(pfc);
    // patch embed -> g_f1 (f32) ; cond embed -> g_qkv (f32, temp)
    launch_gemm(pxh, patchH, patch_b, nullptr, pf1, BATCH * 256, EMBED, 768);
    launch_gemm(pch, condH, cond_b, nullptr, pqkv, BATCH, EMBED, EMBED);
    // assemble + pos + layernorm -> h (d_out)
    ar_assemble_ln<<<MROWS, 256>>>(pf1, pqkv, pos, ln_g, ln_b, h);

    for (int l = 0; l < NB; l++) {
        __half* qkv_l = qkvH + (size_t)l * 1024 * 3072;
        __half* wo_l  = woH  + (size_t)l * 1024 * 1024;
        __half* w1_l  = w1H  + (size_t)l * 1024 * HIDDEN;
        __half* w3_l  = w3H  + (size_t)l * 1024 * HIDDEN;
        __half* w2_l  = w2H  + (size_t)l * HIDDEN * 1024;

        ar_rmsnorm<<<MROWS, 256>>>(h, anw + (size_t)l * EMBED, pa);
        launch_gemm(pa, qkv_l, nullptr, nullptr, pqkv, MROWS, 3 * EMBED, EMBED);
        ar_rope<<<(MROWS * 512 + 255) / 256, 256>>>(pqkv, pfc);
        ar_attn<<<dim3(HEADS, BATCH), 128, SEQ * 64 * 2 * (int)sizeof(float)>>>(pqkv, po);
        ar_attn_last<<<dim3(HEADS, BATCH), 256>>>(pqkv, po);
        launch_gemm(po, wo_l, nullptr, h, h, MROWS, EMBED, EMBED);

        ar_rmsnorm<<<MROWS, 256>>>(h, fnw + (size_t)l * EMBED, pa);
        launch_gemm(pa, w1_l, nullptr, nullptr, pf1, MROWS, HIDDEN, EMBED);
        launch_gemm(pa, w3_l, nullptr, nullptr, pqkv, MROWS, HIDDEN, EMBED);
        ar_silu_mul<<<(MROWS * HIDDEN / 2 + 255) / 256, 256>>>(pf1, pqkv, (__half2*)pu,
                                                               MROWS * HIDDEN / 2);
        launch_gemm(pu, w2_l, nullptr, h, h, MROWS, EMBED, HIDDEN);
    }
}